// round 15
// baseline (speedup 1.0000x reference)
#include <cuda_runtime.h>
#include <cuda_bf16.h>
#include <math.h>
#include <stdint.h>

// Problem constants
static constexpr int kB    = 8;
static constexpr int kS    = 4096;
static constexpr int kH    = 2048;
static constexpr int kHINT = 4;
static constexpr int kNBpB = 512;        // half-blocks per batch
static constexpr int kKDIM = 2052;       // H + HINT
static constexpr int kNW   = 512;        // windows per batch
static constexpr int kMR   = kB * kNBpB; // 4096 GEMM rows = 32 m-tiles of 128
static constexpr int kSPLIT = 8;
static constexpr int kCHUNK = 256;       // last chunk = 2052 - 7*256 = 260

// Scratch: split-K partials
__device__ float g_part[(size_t)kSPLIT * kMR * 64];

// ---------------------------------------------------------------------------
// mma.sync m16n8k16 bf16 (sm_80+ base-target; HMMA on sm_103)
// ---------------------------------------------------------------------------
__device__ __forceinline__ void mma16816(float& d0, float& d1, float& d2, float& d3,
                                         uint32_t a0, uint32_t a1, uint32_t a2, uint32_t a3,
                                         uint32_t b0, uint32_t b1) {
    asm volatile(
        "mma.sync.aligned.m16n8k16.row.col.f32.bf16.bf16.f32 "
        "{%0,%1,%2,%3}, {%4,%5,%6,%7}, {%8,%9}, {%0,%1,%2,%3};"
        : "+f"(d0), "+f"(d1), "+f"(d2), "+f"(d3)
        : "r"(a0), "r"(a1), "r"(a2), "r"(a3), "r"(b0), "r"(b1));
}

// Predicated 16B global load: no branch, request suppressed when w == 0.
__device__ __forceinline__ float4 ldg_pred(const float* p, float w) {
    float4 v = make_float4(0.f, 0.f, 0.f, 0.f);
    asm volatile(
        "{\n\t"
        ".reg .pred p;\n\t"
        "setp.ne.f32 p, %5, 0f00000000;\n\t"
        "@p ld.global.nc.v4.f32 {%0,%1,%2,%3}, [%4];\n\t"
        "}"
        : "+f"(v.x), "+f"(v.y), "+f"(v.z), "+f"(v.w)
        : "l"(p), "f"(w));
    return v;
}

__device__ __forceinline__ uint32_t pack_hi(float x, float y, uint32_t& lo) {
    __nv_bfloat162 h = __float22bfloat162_rn(make_float2(x, y));
    float rx = x - __bfloat162float(__low2bfloat16(h));
    float ry = y - __bfloat162float(__high2bfloat16(h));
    __nv_bfloat162 l = __float22bfloat162_rn(make_float2(rx, ry));
    lo = *reinterpret_cast<uint32_t*>(&l);
    return *reinterpret_cast<uint32_t*>(&h);
}

// smem layout (u32 units), row stride 20 u32 (80B) -> conflict-free frag loads
static constexpr int kRS   = 20;
static constexpr int kAh   = 0;            // 128 rows
static constexpr int kAl   = 128 * kRS;    // 2560
static constexpr int kBh   = 256 * kRS;    // 5120
static constexpr int kBl   = 320 * kRS;    // 6400
static constexpr int kBufU = 384 * kRS;    // 7680 u32 per buffer
static constexpr int kSmemDyn = (2 * kBufU + 1024) * 4;   // + mask floats = 65536 B

// ---------------------------------------------------------------------------
// Fused kernel: masked window pooling + split-precision bf16 tensor GEMM.
// A-fill coalescing: thread t owns 4 k-floats of 4 half-blocks
//   (hb = (t>>3)+32i, kq = (t&7)*4)  ->  8 lanes cover one row's 128B line
//   per LDG.128: 4 lines/warp-LDG, zero L1tex replay.
// ---------------------------------------------------------------------------
__global__ __launch_bounds__(256, 2) void k_fuse(const float* __restrict__ hid,
                                                 const int* __restrict__ am,
                                                 const float* __restrict__ hint,
                                                 const float* __restrict__ W1) {
    extern __shared__ uint32_t su[];
    float* smf = reinterpret_cast<float*>(su + 2 * kBufU);   // 1024 token masks

    const int tid = threadIdx.x;
    const int r0g = blockIdx.x * 128;           // global half-block row base
    const int kc  = blockIdx.y;
    const int kBeg = kc * kCHUNK;
    const int kEnd = (kc == kSPLIT - 1) ? kKDIM : kBeg + kCHUNK;

    const int bat     = r0g >> 9;
    const int tokBase = bat * kS + (r0g & 511) * 8;   // 1024 contiguous tokens

    // token masks -> smem floats
#pragma unroll
    for (int i = 0; i < 4; i++)
        smf[tid + i * 256] = (float)am[tokBase + tid + i * 256];

    const int warp = tid >> 5, lane = tid & 31;
    const int wr = warp & 3, wc = warp >> 2;
    const int wm = wr * 32, wn = wc * 32;
    const int gid = lane >> 2, tig = lane & 3;

    // A-fill mapping: 4 half-blocks per thread, 4 k-floats each
    const int hbq = tid >> 3;          // 0..31; hbs: hbq, +32, +64, +96
    const int kq8 = (tid & 7) * 4;     // k offset in 32-k tile
    // B-fill mapping
    const int bn  = tid >> 2;          // 0..63
    const int bk0 = (tid & 3) * 8;

    const float* arow[4];
#pragma unroll
    for (int i = 0; i < 4; i++)
        arow[i] = hid + (size_t)(tokBase + (hbq + 32 * i) * 8) * kH;
    const float* hrow0 = hint + (size_t)tokBase * kHINT;

    float d[2][4][4];
#pragma unroll
    for (int mt = 0; mt < 2; mt++)
#pragma unroll
        for (int n8 = 0; n8 < 4; n8++)
#pragma unroll
            for (int e = 0; e < 4; e++) d[mt][n8][e] = 0.f;

    float4 acc[4];   // acc[i] = pooled 4 k-floats of hb (hbq + 32i)
    float  rb[8];    // B staging

    __syncthreads();   // masks visible

    auto stage = [&](int t0) {
#pragma unroll
        for (int i = 0; i < 4; i++) acc[i] = make_float4(0.f, 0.f, 0.f, 0.f);
        const int kq0 = t0 + kq8;
        if (kq0 + 4 <= kH) {           // fast path: pure hidden, coalesced v4 loads
#pragma unroll
            for (int i = 0; i < 4; i++) {
                const float* mrow = smf + (hbq + 32 * i) * 8;
#pragma unroll
                for (int j = 0; j < 8; j++) {
                    const float w = mrow[j];   // LDS broadcast across 8 lanes
                    const float4 v = ldg_pred(arow[i] + (size_t)j * kH + kq0, w);
                    acc[i].x += w * v.x; acc[i].y += w * v.y;
                    acc[i].z += w * v.z; acc[i].w += w * v.w;
                }
            }
        } else {                        // tail: hidden/hint/zero per element
#pragma unroll
            for (int i = 0; i < 4; i++) {
                const int hbx = hbq + 32 * i;
                const float* mrow = smf + hbx * 8;
#pragma unroll
                for (int j = 0; j < 8; j++) {
                    const float w = mrow[j];
                    if (w != 0.f) {
                        const float* rp = arow[i] + (size_t)j * kH;
                        const float* hp = hrow0 + (size_t)(hbx * 8 + j) * kHINT;
                        float* a = &acc[i].x;
#pragma unroll
                        for (int e = 0; e < 4; e++) {
                            const int k = kq0 + e;
                            float v = 0.f;
                            if (k < kH) v = rp[k];
                            else if (k < kKDIM) v = hp[k - kH];
                            a[e] += w * v;
                        }
                    }
                }
            }
        }
#pragma unroll
        for (int j = 0; j < 8; j++) {
            const int k = t0 + bk0 + j;
            rb[j] = (k < kKDIM) ? W1[(size_t)k * 64 + bn] : 0.f;
        }
    };

    auto commit = [&](int buf) {
        uint32_t* base = su + buf * kBufU;
#pragma unroll
        for (int i = 0; i < 4; i++) {
            uint32_t l01, l23;
            const uint32_t h01 = pack_hi(acc[i].x, acc[i].y, l01);
            const uint32_t h23 = pack_hi(acc[i].z, acc[i].w, l23);
            const int ci = (hbq + 32 * i) * kRS + (tid & 7) * 2;
            base[kAh + ci] = h01;  base[kAh + ci + 1] = h23;
            base[kAl + ci] = l01;  base[kAl + ci + 1] = l23;
        }
#pragma unroll
        for (int j = 0; j < 8; j += 2) {
            uint32_t l;
            const uint32_t h = pack_hi(rb[j], rb[j + 1], l);
            const int ci = bn * kRS + bk0 / 2 + j / 2;
            base[kBh + ci] = h;
            base[kBl + ci] = l;
        }
    };

    stage(kBeg);
    int buf = 0;
    for (int t0 = kBeg; t0 < kEnd; t0 += 32, buf ^= 1) {
        commit(buf);
        __syncthreads();
        if (t0 + 32 < kEnd) stage(t0 + 32);   // pooling of next tile overlaps MMA

        const uint32_t* sbuf = su + buf * kBufU;
#pragma unroll
        for (int kh = 0; kh < 2; kh++) {
            const int ci = tig + kh * 8;
            uint32_t bh0[4], bh1[4], bl0[4], bl1[4];
#pragma unroll
            for (int n8 = 0; n8 < 4; n8++) {
                const int bro = (wn + n8 * 8 + gid) * kRS + ci;
                bh0[n8] = sbuf[kBh + bro];  bh1[n8] = sbuf[kBh + bro + 4];
                bl0[n8] = sbuf[kBl + bro];  bl1[n8] = sbuf[kBl + bro + 4];
            }
            uint32_t ah[2][4], al[2][4];
#pragma unroll
            for (int mt = 0; mt < 2; mt++) {
                const int r0 = (wm + mt * 16 + gid) * kRS + ci;
                const int r8 = r0 + 8 * kRS;
                ah[mt][0] = sbuf[kAh + r0];      ah[mt][1] = sbuf[kAh + r8];
                ah[mt][2] = sbuf[kAh + r0 + 4];  ah[mt][3] = sbuf[kAh + r8 + 4];
                al[mt][0] = sbuf[kAl + r0];      al[mt][1] = sbuf[kAl + r8];
                al[mt][2] = sbuf[kAl + r0 + 4];  al[mt][3] = sbuf[kAl + r8 + 4];
            }
#pragma unroll
            for (int mt = 0; mt < 2; mt++)
#pragma unroll
                for (int n8 = 0; n8 < 4; n8++) {
                    float* dd = d[mt][n8];
                    mma16816(dd[0], dd[1], dd[2], dd[3],
                             ah[mt][0], ah[mt][1], ah[mt][2], ah[mt][3],
                             bh0[n8], bh1[n8]);
                    mma16816(dd[0], dd[1], dd[2], dd[3],
                             al[mt][0], al[mt][1], al[mt][2], al[mt][3],
                             bh0[n8], bh1[n8]);
                    mma16816(dd[0], dd[1], dd[2], dd[3],
                             ah[mt][0], ah[mt][1], ah[mt][2], ah[mt][3],
                             bl0[n8], bl1[n8]);
                }
        }
        // single barrier per tile: next commit writes the OTHER buffer.
    }

    // epilogue: write partials
    float* pb = g_part + (size_t)kc * kMR * 64;
#pragma unroll
    for (int mt = 0; mt < 2; mt++) {
        const int row0 = r0g + wm + mt * 16 + gid;
#pragma unroll
        for (int n8 = 0; n8 < 4; n8++) {
            const int col = wn + n8 * 8 + tig * 2;
            *reinterpret_cast<float2*>(pb + (size_t)row0 * 64 + col) =
                make_float2(d[mt][n8][0], d[mt][n8][1]);
            *reinterpret_cast<float2*>(pb + (size_t)(row0 + 8) * 64 + col) =
                make_float2(d[mt][n8][2], d[mt][n8][3]);
        }
    }
}

// ---------------------------------------------------------------------------
// Kernel 2: sum split-K partials + adjacent half-block rows, count from raw
// mask, scale, bias, exact gelu, dot W2 -> logits; window_mask.
// One warp per window; lane owns cols {2*lane, 2*lane+1}.
// ---------------------------------------------------------------------------
__global__ __launch_bounds__(256) void k_fin(const int* __restrict__ am,
                                             const float* __restrict__ b1,
                                             const float* __restrict__ W2,
                                             const float* __restrict__ b2,
                                             float* __restrict__ out) {
    const int w    = (blockIdx.x * 256 + threadIdx.x) >> 5;  // 0..4095
    const int lane = threadIdx.x & 31;
    const int b    = w >> 9;
    const int wi   = w & 511;
    const int r0   = b * kNBpB + wi;
    const bool two = (wi < 511);     // window 511's upper half-block is OOB

    float mv = 0.f;
    if (lane < 16) {
        const int p = wi * 8 + lane;
        if (p < kS) mv = (float)am[b * kS + p];
    }
#pragma unroll
    for (int o = 8; o; o >>= 1) mv += __shfl_xor_sync(0xffffffffu, mv, o);
    const float cnt = __shfl_sync(0xffffffffu, mv, 0);
    const float inv = 1.f / fmaxf(cnt, 1.f);
    if (lane == 0) out[kB * kNW + w] = (cnt > 0.f) ? 1.f : 0.f;  // window_mask

    const int c2 = lane * 2;
    float2 s = make_float2(0.f, 0.f);
#pragma unroll
    for (int c = 0; c < kSPLIT; c++) {
        const float* pc = g_part + ((size_t)c * kMR + r0) * 64 + c2;
        const float2 a = *reinterpret_cast<const float2*>(pc);
        s.x += a.x; s.y += a.y;
        if (two) {
            const float2 bb = *reinterpret_cast<const float2*>(pc + 64);
            s.x += bb.x; s.y += bb.y;
        }
    }
    const float x0 = s.x * inv + b1[c2];
    const float x1 = s.y * inv + b1[c2 + 1];
    const float g0 = 0.5f * x0 * (1.f + erff(x0 * 0.70710678118654752f));
    const float g1 = 0.5f * x1 * (1.f + erff(x1 * 0.70710678118654752f));
    float r = g0 * W2[c2] + g1 * W2[c2 + 1];
#pragma unroll
    for (int o = 16; o; o >>= 1) r += __shfl_xor_sync(0xffffffffu, r, o);
    if (lane == 0) out[w] = r + b2[0];   // window_logits
}

extern "C" void kernel_launch(void* const* d_in, const int* in_sizes, int n_in,
                              void* d_out, int out_size) {
    const float* hid  = (const float*)d_in[0];  // hidden_states (8,4096,2048)
    const int*   am   = (const int*)d_in[1];    // attention_mask (8,4096)
    const float* hint = (const float*)d_in[2];  // hint_features (8,4096,4)
    const float* W1   = (const float*)d_in[3];  // (2052,64)
    const float* b1   = (const float*)d_in[4];  // (64,)
    const float* W2   = (const float*)d_in[5];  // (64,1)
    const float* b2   = (const float*)d_in[6];  // (1,)
    float* out = (float*)d_out;                 // [logits (8*512) | mask (8*512)]

    cudaFuncSetAttribute(k_fuse, cudaFuncAttributeMaxDynamicSharedMemorySize,
                         kSmemDyn);

    dim3 g(kMR / 128, kSPLIT);                  // 32 x 8 = 256 CTAs
    k_fuse<<<g, 256, kSmemDyn>>>(hid, am, hint, W1);

    k_fin<<<kB * kNW * 32 / 256, 256>>>(am, b1, W2, b2, out);
}